// round 6
// baseline (speedup 1.0000x reference)
#include <cuda_runtime.h>
#include <cstdint>

// Problem: B=1024, T=365, DYN=32, STATIC=27, U=256, 3U=768, K=288.
#define T_STEPS 365

// -------- device scratch (static; no allocation) --------
__device__ float g_igate[1024 * 256];
__device__ float g_hbuf[2][1024 * 256];
__device__ int   g_bar[16 * 32];     // one counter per gang, 128B apart

// -------- helpers --------
__device__ __forceinline__ uint32_t f2tf(float v) {
    uint32_t r;
    asm("cvt.rna.tf32.f32 %0, %1;" : "=r"(r) : "f"(v));
    return r;
}
__device__ __forceinline__ float tanh_fast(float x) {
    float r;
    asm("tanh.approx.f32 %0, %1;" : "=f"(r) : "f"(x));
    return r;
}
__device__ __forceinline__ float sig_fast(float x) {
    return fmaf(0.5f, tanh_fast(0.5f * x), 0.5f);
}

// ---------------------------------------------------------------------------
// Setup: i_gate = sigmoid(x_static @ W_sh + bias_s); reset gang barriers.
// ---------------------------------------------------------------------------
__global__ void setup_k(const float* __restrict__ xs,
                        const float* __restrict__ wsh,
                        const float* __restrict__ bias_s) {
    int b = blockIdx.x;
    int u = threadIdx.x;
    if (b == 0 && u < 16) g_bar[u * 32] = 0;
    float acc = bias_s[u];
#pragma unroll
    for (int d = 0; d < 27; ++d)
        acc += xs[b * 27 + d] * wsh[d * 256 + u];
    g_igate[b * 256 + u] = sig_fast(acc);
}

// ---------------------------------------------------------------------------
// Main persistent recurrence kernel.
//   gang = blockIdx.x>>3 (16 gangs, 64 batch rows each)
//   ug   = blockIdx.x&7  (8 unit-groups, 32 units -> 96 gate cols each)
// Warp (8) = mt(4 m-tiles of 16 rows) x nh(2 col-halves of 48 cols).
// Column permutation: phys col (nt, c) within a warp-half maps to
//   j = nt*2 + (c&1); gate = j%3; unit_in_half = (c>>1)*4 + j/3
// so each thread's 12 C-columns = 4 units x {f,o,g}  -> epilogue in registers.
// Smem: sW [96][148] float2 tf32 B-frags (28416 w) + sA [64][292] tf32 (18688 w)
// ---------------------------------------------------------------------------
#define SW_WORDS 28416
#define SA_WORDS 18688
#define SMEM_BYTES ((SW_WORDS + SA_WORDS) * 4)   // 188416 B

__global__ void __launch_bounds__(256, 1)
lstm_k(const float* __restrict__ xd,
       const float* __restrict__ wih,
       const float* __restrict__ whh,
       const float* __restrict__ bias,
       float* __restrict__ out) {
    extern __shared__ uint32_t smem[];
    uint32_t* sW = smem;
    uint32_t* sA = smem + SW_WORDS;

    const int tid  = threadIdx.x;
    const int lane = tid & 31;
    const int warp = tid >> 5;
    const int bt   = blockIdx.x >> 3;
    const int ug   = blockIdx.x & 7;
    const int b0   = bt * 64;
    const int U0   = ug * 32;

    // ---- one-time: pack permuted W slice [288 x 96] into B-frag layout ----
    for (int idx = tid; idx < 288 * 96; idx += 256) {
        int k = idx / 96;
        int n = idx - k * 96;              // physical col 0..95
        int nhp = n / 48;
        int nn  = n - nhp * 48;
        int ntp = nn >> 3;
        int c   = nn & 7;
        int j    = ntp * 2 + (c & 1);
        int gate = j % 3;
        int unitw = (c >> 1) * 4 + j / 3;
        int gcol = gate * 256 + U0 + nhp * 16 + unitw;
        float v = (k < 256) ? whh[k * 768 + gcol] : wih[(k - 256) * 768 + gcol];
        int kt = k >> 3, kk = k & 7;
        sW[(n * 148 + kt * 4 + (kk & 3)) * 2 + (kk >> 2)] = f2tf(v);
    }

    // ---- zero the h region of sA (only needed for t=0) ----
    {
        uint4 z = make_uint4(0, 0, 0, 0);
#pragma unroll
        for (int i = 0; i < 16; ++i) {
            int idx = tid + (i << 8);            // 0..4095 uint4
            int m = idx >> 6, q = idx & 63;
            *(uint4*)&sA[m * 292 + q * 4] = z;
        }
    }

    // ---- MMA role & per-thread persistent state ----
    const int mt  = warp & 3;
    const int nh  = warp >> 2;
    const int gid = lane >> 2;
    const int tig = lane & 3;
    const int row0 = b0 + mt * 16 + gid;          // second row = row0 + 8
    const int ucol = U0 + nh * 16 + tig * 4;      // 4 consecutive units

    float cst[2][4], igr[2][4], bfv[4], bov[4], bgv[4];
    {
        float4 i0 = *(const float4*)&g_igate[row0 * 256 + ucol];
        float4 i1 = *(const float4*)&g_igate[(row0 + 8) * 256 + ucol];
        igr[0][0] = i0.x; igr[0][1] = i0.y; igr[0][2] = i0.z; igr[0][3] = i0.w;
        igr[1][0] = i1.x; igr[1][1] = i1.y; igr[1][2] = i1.z; igr[1][3] = i1.w;
#pragma unroll
        for (int q = 0; q < 4; ++q) {
            cst[0][q] = 0.0f; cst[1][q] = 0.0f;
            bfv[q] = bias[ucol + q];
            bov[q] = bias[256 + ucol + q];
            bgv[q] = bias[512 + ucol + q];
        }
    }

    const uint32_t* A0b = sA + (mt * 16 + gid) * 292 + tig;
    const uint32_t* A1b = A0b + 8 * 292;
    int* barp = &g_bar[bt * 32];

    __syncthreads();   // W packed, h region zeroed

    for (int t = 0; t < T_STEPS; ++t) {
        // ---- stage x_t (independent of h) ----
#pragma unroll
        for (int i = 0; i < 2; ++i) {
            int idx = warp + i * 8;                       // 0..15
            int m  = idx * 4 + (lane >> 3);
            int cc = (lane & 7) * 4;
            float4 v = *(const float4*)&xd[((size_t)(b0 + m) * 365 + t) * 32 + cc];
            uint4 w;
            w.x = f2tf(v.x); w.y = f2tf(v.y); w.z = f2tf(v.z); w.w = f2tf(v.w);
            *(uint4*)&sA[m * 292 + 256 + cc] = w;
        }
        __syncthreads();                                   // s1

        // ---- x-part MMA (kt 32..35) while producers finish h_t ----
        float acc[6][4];
#pragma unroll
        for (int nt = 0; nt < 6; ++nt)
#pragma unroll
            for (int q = 0; q < 4; ++q) acc[nt][q] = 0.0f;

#pragma unroll
        for (int kt = 32; kt < 36; ++kt) {
            uint32_t a0 = A0b[kt * 8];
            uint32_t a2 = A0b[kt * 8 + 4];
            uint32_t a1 = A1b[kt * 8];
            uint32_t a3 = A1b[kt * 8 + 4];
#pragma unroll
            for (int nt = 0; nt < 6; ++nt) {
                const uint32_t* bp =
                    sW + ((nh * 48 + nt * 8 + gid) * 148 + kt * 4 + tig) * 2;
                uint2 bv = *(const uint2*)bp;
                asm volatile(
                    "mma.sync.aligned.m16n8k8.row.col.f32.tf32.tf32.f32 "
                    "{%0,%1,%2,%3}, {%4,%5,%6,%7}, {%8,%9}, {%0,%1,%2,%3};"
                    : "+f"(acc[nt][0]), "+f"(acc[nt][1]),
                      "+f"(acc[nt][2]), "+f"(acc[nt][3])
                    : "r"(a0), "r"(a1), "r"(a2), "r"(a3),
                      "r"(bv.x), "r"(bv.y));
            }
        }

        // ---- gang barrier: wait for h_t from all 8 unit-group CTAs ----
        if (t > 0) {
            if (tid == 0) {
                int target = t * 8, v;
                do {
                    asm volatile("ld.acquire.gpu.global.b32 %0, [%1];"
                                 : "=r"(v) : "l"(barp) : "memory");
                } while (v < target);
            }
            __syncthreads();                               // s2

            // ---- stage h_t (tf32) ----
            const float* hb = g_hbuf[t & 1];
#pragma unroll
            for (int i = 0; i < 16; ++i) {
                int idx  = warp + i * 8;                  // 0..127
                int m    = idx >> 1;
                int half = (idx & 1) << 7;
                float4 v = *(const float4*)&hb[(b0 + m) * 256 + half + lane * 4];
                uint4 w;
                w.x = f2tf(v.x); w.y = f2tf(v.y); w.z = f2tf(v.z); w.w = f2tf(v.w);
                *(uint4*)&sA[m * 292 + half + lane * 4] = w;
            }
            __syncthreads();                               // s3
        }

        // ---- h-part MMA (kt 0..31) ----
#pragma unroll 4
        for (int kt = 0; kt < 32; ++kt) {
            uint32_t a0 = A0b[kt * 8];
            uint32_t a2 = A0b[kt * 8 + 4];
            uint32_t a1 = A1b[kt * 8];
            uint32_t a3 = A1b[kt * 8 + 4];
#pragma unroll
            for (int nt = 0; nt < 6; ++nt) {
                const uint32_t* bp =
                    sW + ((nh * 48 + nt * 8 + gid) * 148 + kt * 4 + tig) * 2;
                uint2 bv = *(const uint2*)bp;
                asm volatile(
                    "mma.sync.aligned.m16n8k8.row.col.f32.tf32.tf32.f32 "
                    "{%0,%1,%2,%3}, {%4,%5,%6,%7}, {%8,%9}, {%0,%1,%2,%3};"
                    : "+f"(acc[nt][0]), "+f"(acc[nt][1]),
                      "+f"(acc[nt][2]), "+f"(acc[nt][3])
                    : "r"(a0), "r"(a1), "r"(a2), "r"(a3),
                      "r"(bv.x), "r"(bv.y));
            }
        }

        // ---- epilogue fully in registers ----
        // per row r (slots sb=2r): unit q gates:
        //  q0: f=acc[0][sb]   o=acc[0][sb+1] g=acc[1][sb]
        //  q1: f=acc[1][sb+1] o=acc[2][sb]   g=acc[2][sb+1]
        //  q2: f=acc[3][sb]   o=acc[3][sb+1] g=acc[4][sb]
        //  q3: f=acc[4][sb+1] o=acc[5][sb]   g=acc[5][sb+1]
        float* dst = (t < T_STEPS - 1) ? g_hbuf[(t + 1) & 1] : out;
#pragma unroll
        for (int r = 0; r < 2; ++r) {
            const int sb = 2 * r;
            float fg[4] = { acc[0][sb],     acc[1][sb + 1],
                            acc[3][sb],     acc[4][sb + 1] };
            float og[4] = { acc[0][sb + 1], acc[2][sb],
                            acc[3][sb + 1], acc[5][sb] };
            float gg[4] = { acc[1][sb],     acc[2][sb + 1],
                            acc[4][sb],     acc[5][sb + 1] };
            float hv[4];
#pragma unroll
            for (int q = 0; q < 4; ++q) {
                float cn = sig_fast(fg[q] + bfv[q]) * cst[r][q]
                         + igr[r][q] * tanh_fast(gg[q] + bgv[q]);
                cst[r][q] = cn;
                hv[q] = sig_fast(og[q] + bov[q]) * tanh_fast(cn);
            }
            *(float4*)&dst[(row0 + 8 * r) * 256 + ucol] =
                make_float4(hv[0], hv[1], hv[2], hv[3]);
        }

        // ---- publish h_{t+1} ----
        if (t < T_STEPS - 1) {
            __threadfence();
            __syncthreads();                               // s4 (loop boundary)
            if (tid == 0)
                asm volatile("red.release.gpu.global.add.s32 [%0], %1;"
                             :: "l"(barp), "r"(1) : "memory");
        }
    }
}

// ---------------------------------------------------------------------------
extern "C" void kernel_launch(void* const* d_in, const int* in_sizes, int n_in,
                              void* d_out, int out_size) {
    const float* xd     = (const float*)d_in[0];   // x_dynamic [1024,365,32]
    const float* xs     = (const float*)d_in[1];   // x_static  [1024,27]
    const float* wih    = (const float*)d_in[2];   // weight_ih [32,768]
    const float* whh    = (const float*)d_in[3];   // weight_hh [256,768]
    const float* wsh    = (const float*)d_in[4];   // weight_sh [27,256]
    const float* bias   = (const float*)d_in[5];   // [768]
    const float* bias_s = (const float*)d_in[6];   // [256]
    float* out = (float*)d_out;                    // [1024,256]

    cudaFuncSetAttribute(lstm_k, cudaFuncAttributeMaxDynamicSharedMemorySize,
                         SMEM_BYTES);

    setup_k<<<1024, 256>>>(xs, wsh, bias_s);
    lstm_k<<<128, 256, SMEM_BYTES>>>(xd, wih, whh, bias, out);
}

// round 8
// speedup vs baseline: 1.0849x; 1.0849x over previous
#include <cuda_runtime.h>
#include <cstdint>

// Problem: B=1024, T=365, DYN=32, STATIC=27, U=256, 3U=768, K=288.
#define T_STEPS 365

// -------- device scratch (static; no allocation) --------
__device__ float g_igate[1024 * 256];
__device__ float g_hbuf[2][1024 * 256];
__device__ int   g_flag[16 * 64];    // flag[bt*64 + ug*8], 32B apart

// -------- helpers --------
__device__ __forceinline__ uint32_t f2tf(float v) {
    uint32_t r;
    asm("cvt.rna.tf32.f32 %0, %1;" : "=r"(r) : "f"(v));
    return r;
}
__device__ __forceinline__ float tanh_fast(float x) {
    float r;
    asm("tanh.approx.f32 %0, %1;" : "=f"(r) : "f"(x));
    return r;
}
__device__ __forceinline__ float sig_fast(float x) {
    return fmaf(0.5f, tanh_fast(0.5f * x), 0.5f);
}
__device__ __forceinline__ void mma_tf32(float acc[4], uint32_t a0, uint32_t a1,
                                         uint32_t a2, uint32_t a3,
                                         uint32_t b0, uint32_t b1) {
    asm volatile(
        "mma.sync.aligned.m16n8k8.row.col.f32.tf32.tf32.f32 "
        "{%0,%1,%2,%3}, {%4,%5,%6,%7}, {%8,%9}, {%0,%1,%2,%3};"
        : "+f"(acc[0]), "+f"(acc[1]), "+f"(acc[2]), "+f"(acc[3])
        : "r"(a0), "r"(a1), "r"(a2), "r"(a3), "r"(b0), "r"(b1));
}

// ---------------------------------------------------------------------------
// Setup: i_gate = sigmoid(x_static @ W_sh + bias_s); reset flags.
// ---------------------------------------------------------------------------
__global__ void setup_k(const float* __restrict__ xs,
                        const float* __restrict__ wsh,
                        const float* __restrict__ bias_s) {
    int b = blockIdx.x;
    int u = threadIdx.x;
    if (b == 0) {
#pragma unroll
        for (int i = 0; i < 4; ++i) g_flag[u + i * 256] = 0;
    }
    float acc = bias_s[u];
#pragma unroll
    for (int d = 0; d < 27; ++d)
        acc += xs[b * 27 + d] * wsh[d * 256 + u];
    g_igate[b * 256 + u] = sig_fast(acc);
}

// ---------------------------------------------------------------------------
// Main persistent recurrence kernel.
//   gang = blockIdx.x>>3 (16 gangs, 64 batch rows each)
//   ug   = blockIdx.x&7  (8 unit-groups, 32 units -> 96 gate cols each)
// Warp (8) = mt(4 m-tiles of 16 rows) x nh(2 col-halves of 48 cols).
// Column permutation (unchanged from R5): each thread's 12 C-cols = 4 units
// x {f,o,g} -> epilogue fully in registers.
// Smem: sW [96][304] words, kt-pair packed tf32 B-frags (uint4 per (nt,ktp))
//       sA [64][292] words, natural-layout tf32 A rows
// ---------------------------------------------------------------------------
#define SW_WORDS (96 * 304)          // 29184
#define SA_WORDS (64 * 292)          // 18688
#define SMEM_BYTES ((SW_WORDS + SA_WORDS) * 4)   // 191488 B

__global__ void __launch_bounds__(256, 1)
lstm_k(const float* __restrict__ xd,
       const float* __restrict__ wih,
       const float* __restrict__ whh,
       const float* __restrict__ bias,
       float* __restrict__ out) {
    extern __shared__ uint32_t smem[];
    uint32_t* sW = smem;
    uint32_t* sA = smem + SW_WORDS;

    const int tid  = threadIdx.x;
    const int lane = tid & 31;
    const int warp = tid >> 5;
    const int bt   = blockIdx.x >> 3;
    const int ug   = blockIdx.x & 7;
    const int b0   = bt * 64;
    const int U0   = ug * 32;

    // ---- one-time: pack permuted W slice [288 x 96], kt-pair uint4 layout --
    // word idx = n*304 + (kt>>1)*16 + (kk&3)*4 + (kt&1)*2 + (kk>>2)
    for (int idx = tid; idx < 288 * 96; idx += 256) {
        int k = idx / 96;
        int n = idx - k * 96;              // physical col 0..95
        int nhp = n / 48;
        int nn  = n - nhp * 48;
        int ntp = nn >> 3;
        int c   = nn & 7;
        int j    = ntp * 2 + (c & 1);
        int gate = j % 3;
        int unitw = (c >> 1) * 4 + j / 3;
        int gcol = gate * 256 + U0 + nhp * 16 + unitw;
        float v = (k < 256) ? whh[k * 768 + gcol] : wih[(k - 256) * 768 + gcol];
        int kt = k >> 3, kk = k & 7;
        sW[n * 304 + (kt >> 1) * 16 + (kk & 3) * 4 + (kt & 1) * 2 + (kk >> 2)]
            = f2tf(v);
    }

    // ---- zero the h region of sA (for t=0) ----
    {
        uint4 z = make_uint4(0, 0, 0, 0);
#pragma unroll
        for (int i = 0; i < 16; ++i) {
            int idx = tid + (i << 8);            // 0..4095 uint4
            int m = idx >> 6, q = idx & 63;
            *(uint4*)&sA[m * 292 + q * 4] = z;
        }
    }

    // ---- MMA role & per-thread persistent state ----
    const int mt  = warp & 3;
    const int nh  = warp >> 2;
    const int gid = lane >> 2;
    const int tig = lane & 3;
    const int row0 = b0 + mt * 16 + gid;          // second row = row0 + 8
    const int ucol = U0 + nh * 16 + tig * 4;      // 4 consecutive units

    float cst[2][4], igr[2][4], bfv[4], bov[4], bgv[4];
    {
        float4 i0 = *(const float4*)&g_igate[row0 * 256 + ucol];
        float4 i1 = *(const float4*)&g_igate[(row0 + 8) * 256 + ucol];
        igr[0][0] = i0.x; igr[0][1] = i0.y; igr[0][2] = i0.z; igr[0][3] = i0.w;
        igr[1][0] = i1.x; igr[1][1] = i1.y; igr[1][2] = i1.z; igr[1][3] = i1.w;
#pragma unroll
        for (int q = 0; q < 4; ++q) {
            cst[0][q] = 0.0f; cst[1][q] = 0.0f;
            bfv[q] = bias[ucol + q];
            bov[q] = bias[256 + ucol + q];
            bgv[q] = bias[512 + ucol + q];
        }
    }

    const uint32_t* A0b = sA + (mt * 16 + gid) * 292 + tig;
    const uint32_t* A1b = A0b + 8 * 292;
    // B-frag base pointers per nt (uint4 loads at + ktp*16)
    const uint32_t* wb0 = sW + (nh * 48 + gid) * 304 + tig * 4;

    const uint32_t sAsh = (uint32_t)__cvta_generic_to_shared(sA);
    int* flag_self = &g_flag[bt * 64 + ug * 8];
    const int* flag_w = &g_flag[bt * 64 + warp * 8];

    // x staging role (per warp): rows m = warp*4.. pattern, 2 iters
    const int xm0 = warp * 4 + (lane >> 3);
    const int xcc = (lane & 7) * 4;

    // ---- preload x_0 into registers ----
    float4 px[2];
#pragma unroll
    for (int i = 0; i < 2; ++i) {
        int m = xm0 + i * 32;
        px[i] = *(const float4*)&xd[((size_t)(b0 + m) * 365 + 0) * 32 + xcc];
    }

    __syncthreads();   // W packed, h region zeroed

    for (int t = 0; t < T_STEPS; ++t) {
        // ---- store x_t from prefetched registers (cvt to tf32) ----
#pragma unroll
        for (int i = 0; i < 2; ++i) {
            int m = xm0 + i * 32;
            uint4 w;
            w.x = f2tf(px[i].x); w.y = f2tf(px[i].y);
            w.z = f2tf(px[i].z); w.w = f2tf(px[i].w);
            *(uint4*)&sA[m * 292 + 256 + xcc] = w;
        }
        __syncthreads();                                   // s1

        // ---- x-part MMA (ktp 16..17) while producers finish h_t ----
        float acc[6][4];
#pragma unroll
        for (int nt = 0; nt < 6; ++nt)
#pragma unroll
            for (int q = 0; q < 4; ++q) acc[nt][q] = 0.0f;

#pragma unroll
        for (int ktp = 16; ktp < 18; ++ktp) {
            uint32_t a0e = A0b[ktp * 16],      a2e = A0b[ktp * 16 + 4];
            uint32_t a1e = A1b[ktp * 16],      a3e = A1b[ktp * 16 + 4];
            uint32_t a0o = A0b[ktp * 16 + 8],  a2o = A0b[ktp * 16 + 12];
            uint32_t a1o = A1b[ktp * 16 + 8],  a3o = A1b[ktp * 16 + 12];
#pragma unroll
            for (int nt = 0; nt < 6; ++nt) {
                uint4 bq = *(const uint4*)(wb0 + nt * 8 * 304 + ktp * 16);
                mma_tf32(acc[nt], a0e, a1e, a2e, a3e, bq.x, bq.y);
                mma_tf32(acc[nt], a0o, a1o, a2o, a3o, bq.z, bq.w);
            }
        }

        // ---- per-warp: wait for producer `warp`, cp.async its h chunk ----
        if (t > 0) {
            int v;
            do {
                asm volatile("ld.acquire.gpu.global.b32 %0, [%1];"
                             : "=r"(v) : "l"(flag_w) : "memory");
            } while (v < t);
            const float* hb = g_hbuf[t & 1];
#pragma unroll
            for (int i = 0; i < 16; ++i) {
                int idx = lane + (i << 5);        // 0..511
                int row = idx >> 3;
                int seg = (idx & 7) << 2;
                const float* src = &hb[(b0 + row) * 256 + warp * 32 + seg];
                uint32_t dst = sAsh + (row * 292 + warp * 32 + seg) * 4;
                asm volatile("cp.async.cg.shared.global [%0], [%1], 16;"
                             :: "r"(dst), "l"(src));
            }
            asm volatile("cp.async.commit_group;");
        }

        // ---- prefetch x_{t+1} (hidden behind staging + h-MMA) ----
        if (t + 1 < T_STEPS) {
#pragma unroll
            for (int i = 0; i < 2; ++i) {
                int m = xm0 + i * 32;
                px[i] = *(const float4*)
                    &xd[((size_t)(b0 + m) * 365 + (t + 1)) * 32 + xcc];
            }
        }

        if (t > 0) {
            asm volatile("cp.async.wait_group 0;");
            __syncthreads();                               // s3
        }

        // ---- h-part MMA (ktp 0..15) ----
#pragma unroll 4
        for (int ktp = 0; ktp < 16; ++ktp) {
            uint32_t a0e = A0b[ktp * 16],      a2e = A0b[ktp * 16 + 4];
            uint32_t a1e = A1b[ktp * 16],      a3e = A1b[ktp * 16 + 4];
            uint32_t a0o = A0b[ktp * 16 + 8],  a2o = A0b[ktp * 16 + 12];
            uint32_t a1o = A1b[ktp * 16 + 8],  a3o = A1b[ktp * 16 + 12];
#pragma unroll
            for (int nt = 0; nt < 6; ++nt) {
                uint4 bq = *(const uint4*)(wb0 + nt * 8 * 304 + ktp * 16);
                mma_tf32(acc[nt], a0e, a1e, a2e, a3e, bq.x, bq.y);
                mma_tf32(acc[nt], a0o, a1o, a2o, a3o, bq.z, bq.w);
            }
        }

        // ---- epilogue fully in registers ----
        if (t < T_STEPS - 1) {
            float* hb = g_hbuf[(t + 1) & 1];
#pragma unroll
            for (int r = 0; r < 2; ++r) {
                const int sb = 2 * r;
                float fg[4] = { acc[0][sb],     acc[1][sb + 1],
                                acc[3][sb],     acc[4][sb + 1] };
                float og[4] = { acc[0][sb + 1], acc[2][sb],
                                acc[3][sb + 1], acc[5][sb] };
                float gg[4] = { acc[1][sb],     acc[2][sb + 1],
                                acc[4][sb],     acc[5][sb + 1] };
                uint4 hw;
                uint32_t* hwp = &hw.x;
#pragma unroll
                for (int q = 0; q < 4; ++q) {
                    float cn = sig_fast(fg[q] + bfv[q]) * cst[r][q]
                             + igr[r][q] * tanh_fast(gg[q] + bgv[q]);
                    cst[r][q] = cn;
                    float hv = sig_fast(og[q] + bov[q]) * tanh_fast(cn);
                    hwp[q] = f2tf(hv);   // pre-round: consumers copy raw bits
                }
                *(uint4*)&hb[(row0 + 8 * r) * 256 + ucol] = hw;
            }
            __syncthreads();                               // s4
            if (tid == 0)
                asm volatile("st.release.gpu.global.b32 [%0], %1;"
                             :: "l"(flag_self), "r"(t + 1) : "memory");
        } else {
#pragma unroll
            for (int r = 0; r < 2; ++r) {
                const int sb = 2 * r;
                float fg[4] = { acc[0][sb],     acc[1][sb + 1],
                                acc[3][sb],     acc[4][sb + 1] };
                float og[4] = { acc[0][sb + 1], acc[2][sb],
                                acc[3][sb + 1], acc[5][sb] };
                float gg[4] = { acc[1][sb],     acc[2][sb + 1],
                                acc[4][sb],     acc[5][sb + 1] };
                float hv[4];
#pragma unroll
                for (int q = 0; q < 4; ++q) {
                    float cn = sig_fast(fg[q] + bfv[q]) * cst[r][q]
                             + igr[r][q] * tanh_fast(gg[q] + bgv[q]);
                    hv[q] = sig_fast(og[q] + bov[q]) * tanh_fast(cn);
                }
                *(float4*)&out[(row0 + 8 * r) * 256 + ucol] =
                    make_float4(hv[0], hv[1], hv[2], hv[3]);
            }
        }
    }
}

// ---------------------------------------------------------------------------
extern "C" void kernel_launch(void* const* d_in, const int* in_sizes, int n_in,
                              void* d_out, int out_size) {
    const float* xd     = (const float*)d_in[0];   // x_dynamic [1024,365,32]
    const float* xs     = (const float*)d_in[1];   // x_static  [1024,27]
    const float* wih    = (const float*)d_in[2];   // weight_ih [32,768]
    const float* whh    = (const float*)d_in[3];   // weight_hh [256,768]
    const float* wsh    = (const float*)d_in[4];   // weight_sh [27,256]
    const float* bias   = (const float*)d_in[5];   // [768]
    const float* bias_s = (const float*)d_in[6];   // [256]
    float* out = (float*)d_out;                    // [1024,256]

    cudaFuncSetAttribute(lstm_k, cudaFuncAttributeMaxDynamicSharedMemorySize,
                         SMEM_BYTES);

    setup_k<<<1024, 256>>>(xs, wsh, bias_s);
    lstm_k<<<128, 256, SMEM_BYTES>>>(xd, wih, whh, bias, out);
}